// round 13
// baseline (speedup 1.0000x reference)
#include <cuda_runtime.h>
#include <cuda_fp16.h>
#include <cstdint>
#include <math.h>

#define BB    4
#define TSEQ  2048
#define CDIM  1024
#define HEADS 16
#define DHEAD 64
#define MTOT  (BB * TSEQ)
#define FDIM  (4 * CDIM)
#define C3    (3 * CDIM)

// -------- scratch (device globals) --------
__device__ __half g_h   [MTOT * CDIM];
__device__ __half g_qkv [MTOT * C3];
__device__ __half g_a   [MTOT * CDIM];
__device__ float  g_x1  [MTOT * CDIM];
__device__ __half g_ff  [MTOT * FDIM];
__device__ __half g_Wqkv[CDIM * C3];
__device__ __half g_Wo[CDIM * CDIM];
__device__ __half g_W1[CDIM * FDIM], g_W2[FDIM * CDIM];

// -------- PTX helpers (plain sm_80+ only) --------
__device__ __forceinline__ uint32_t smem_u32(const void* p) {
    uint32_t a;
    asm("{ .reg .u64 t; cvta.to.shared.u64 t, %1; cvt.u32.u64 %0, t; }" : "=r"(a) : "l"(p));
    return a;
}
__device__ __forceinline__ void cp16(uint32_t dst, const void* src) {
    asm volatile("cp.async.cg.shared.global [%0], [%1], 16;" :: "r"(dst), "l"(src));
}
__device__ __forceinline__ void cp_commit() { asm volatile("cp.async.commit_group;"); }
template<int N> __device__ __forceinline__ void cp_wait() {
    asm volatile("cp.async.wait_group %0;" :: "n"(N));
}
__device__ __forceinline__ void ldsm_x4(uint32_t* r, uint32_t a) {
    asm volatile("ldmatrix.sync.aligned.m8n8.x4.shared.b16 {%0,%1,%2,%3}, [%4];"
                 : "=r"(r[0]), "=r"(r[1]), "=r"(r[2]), "=r"(r[3]) : "r"(a));
}
__device__ __forceinline__ void ldsm_x4t(uint32_t* r, uint32_t a) {
    asm volatile("ldmatrix.sync.aligned.m8n8.x4.trans.shared.b16 {%0,%1,%2,%3}, [%4];"
                 : "=r"(r[0]), "=r"(r[1]), "=r"(r[2]), "=r"(r[3]) : "r"(a));
}
__device__ __forceinline__ void mma_f16(float* c, const uint32_t* a, const uint32_t* b) {
    asm volatile(
        "mma.sync.aligned.m16n8k16.row.col.f32.f16.f16.f32 "
        "{%0,%1,%2,%3}, {%4,%5,%6,%7}, {%8,%9}, {%0,%1,%2,%3};"
        : "+f"(c[0]), "+f"(c[1]), "+f"(c[2]), "+f"(c[3])
        : "r"(a[0]), "r"(a[1]), "r"(a[2]), "r"(a[3]), "r"(b[0]), "r"(b[1]));
}
__device__ __forceinline__ uint32_t packh2(float a, float b) {
    __half2 h = __floats2half2_rn(a, b);
    return *(uint32_t*)&h;
}
__device__ __forceinline__ float fexp2(float t) {   // fast 2^t, t<=0
    t = fmaxf(t, -126.0f);
    const float mag = 12582912.0f;
    float r = t + mag;
    uint32_t ui = __float_as_uint(r);
    float f = t - (r - mag);
    float p = 1.3333558146e-3f;
    p = fmaf(p, f, 9.6181291076e-3f);
    p = fmaf(p, f, 5.5504108664e-2f);
    p = fmaf(p, f, 2.4022650696e-1f);
    p = fmaf(p, f, 6.9314718056e-1f);
    p = fmaf(p, f, 1.0f);
    return __uint_as_float(__float_as_uint(p) + (ui << 23));
}

// ==================== fp16 GEMM: 128x128 CTA, 64x32 warp tile =============
// 8 warps (2x4), BK=64, 2-stage cp.async, 2 CTAs/SM, ONE barrier per chunk.
// OUT: 0 = fp32 (+res), 2 = single fp16.
#define GT       256
#define GA2      18432   // 128 rows x 144B (64 fp16 + pad)
#define GB2      17408   // 64 rows x 272B (128 fp16 + pad)
#define GSTG     (GA2 + GB2)        // 35840
#define GEMM_SMEM (2 * GSTG)        // 71680

template<bool BIAS, bool RELU, bool RES, int OUT>
__global__ void __launch_bounds__(GT, 2) gemm16(
    const __half* __restrict__ A, const __half* __restrict__ B,
    const float* __restrict__ bias, const float* __restrict__ res,
    float* __restrict__ Cf, __half* __restrict__ Ch,
    int N, int K)
{
    extern __shared__ char sm[];
    const uint32_t sb = smem_u32(sm);
    const int tid = threadIdx.x, lane = tid & 31, wid = tid >> 5;
    const int wm = (wid >> 2) * 64, wn = (wid & 3) * 32;
    const int m0 = blockIdx.y * 128, n0 = blockIdx.x * 128;

    auto load_stage = [&](int s, int c) {
        const int kc = c << 6;
        const uint32_t st = sb + (uint32_t)s * GSTG;
        // A: 128 rows x 128B; thread: row = tid/2, 4 consecutive 16B segs
        const int row = tid >> 1, sg0 = (tid & 1) << 2;
        const size_t g = (size_t)(m0 + row) * K + kc + sg0 * 8;
        const uint32_t so = st + row * 144 + sg0 * 16;
        cp16(so,      A + g);
        cp16(so + 16, A + g + 8);
        cp16(so + 32, A + g + 16);
        cp16(so + 48, A + g + 24);
        // B: 64 rows x 256B; thread: rows {tid/16 + 16j}, seg tid%16
        const int br = tid >> 4, seg = tid & 15;
        #pragma unroll
        for (int j = 0; j < 4; j++) {
            const size_t gb = (size_t)(kc + br + 16 * j) * N + n0 + seg * 8;
            cp16(st + GA2 + (br + 16 * j) * 272 + seg * 16, B + gb);
        }
    };

    float acc[4][4][4];
    #pragma unroll
    for (int a = 0; a < 4; a++)
        #pragma unroll
        for (int b = 0; b < 4; b++)
            #pragma unroll
            for (int d = 0; d < 4; d++) acc[a][b][d] = 0.f;

    const int NC = K >> 6;
    load_stage(0, 0); cp_commit();

    for (int c = 0; c < NC; c++) {
        const int s = c & 1;
        cp_wait<0>();          // drain load(c)
        __syncthreads();       // all warps done computing stage s^1 (iter c-1)
        if (c + 1 < NC) { load_stage(s ^ 1, c + 1); cp_commit(); }

        const uint32_t aoff = sb + (uint32_t)s * GSTG;
        const uint32_t boff = aoff + GA2;
        #pragma unroll
        for (int ks = 0; ks < 4; ks++) {
            uint32_t bfr[4][2];
            #pragma unroll
            for (int ntp = 0; ntp < 2; ntp++) {
                uint32_t r[4];
                ldsm_x4t(r, boff + (ks * 16 + (lane & 15)) * 272
                              + (wn + ntp * 16 + ((lane >> 4) << 3)) * 2);
                bfr[2*ntp][0] = r[0]; bfr[2*ntp][1] = r[1];
                bfr[2*ntp+1][0] = r[2]; bfr[2*ntp+1][1] = r[3];
            }
            #pragma unroll
            for (int mt = 0; mt < 4; mt++) {
                uint32_t ah[4];
                ldsm_x4(ah, aoff + (wm + mt * 16 + (lane & 15)) * 144
                              + (ks * 16 + ((lane >> 4) << 3)) * 2);
                #pragma unroll
                for (int nt = 0; nt < 4; nt++)
                    mma_f16(acc[mt][nt], ah, bfr[nt]);
            }
        }
    }

    #pragma unroll
    for (int mt = 0; mt < 4; mt++)
        #pragma unroll
        for (int nt = 0; nt < 4; nt++)
            #pragma unroll
            for (int hf = 0; hf < 2; hf++) {
                const int row = m0 + wm + mt * 16 + (lane >> 2) + hf * 8;
                const int col = n0 + wn + nt * 8 + (lane & 3) * 2;
                float v0 = acc[mt][nt][hf * 2 + 0];
                float v1 = acc[mt][nt][hf * 2 + 1];
                if (BIAS) { v0 += bias[col]; v1 += bias[col + 1]; }
                if (RELU) { v0 = fmaxf(v0, 0.f); v1 = fmaxf(v1, 0.f); }
                if (RES) {
                    const float2 rr = *(const float2*)&res[(size_t)row * N + col];
                    v0 += rr.x; v1 += rr.y;
                }
                if (OUT == 2) {
                    *(uint32_t*)&Ch[(size_t)row * N + col] = packh2(v0, v1);
                } else {
                    float2 o; o.x = v0; o.y = v1;
                    *(float2*)&Cf[(size_t)row * N + col] = o;
                }
            }
}

// ==================== weight converts ====================
__global__ void __launch_bounds__(256) wconv_kernel(
    const float* __restrict__ w, __half* __restrict__ o, int n4)
{
    for (int i = blockIdx.x * blockDim.x + threadIdx.x; i < n4;
         i += gridDim.x * blockDim.x) {
        const float4 v = ((const float4*)w)[i];
        const __half2 a = __floats2half2_rn(v.x, v.y);
        const __half2 b = __floats2half2_rn(v.z, v.w);
        uint2 u; u.x = *(const uint32_t*)&a; u.y = *(const uint32_t*)&b;
        *(uint2*)&o[(size_t)i * 4] = u;
    }
}
__global__ void __launch_bounds__(256) wconv_qkv_kernel(
    const float* __restrict__ Wq, const float* __restrict__ Wk,
    const float* __restrict__ Wv, __half* __restrict__ dst)
{
    const int z = blockIdx.z;
    const float* w = (z == 0) ? Wq : (z == 1) ? Wk : Wv;
    const int coff = z * CDIM;
    const int idx = blockIdx.x * blockDim.x + threadIdx.x;
    const int row = idx >> 7;
    const int g8  = idx & 127;
    const float4 v0 = *(const float4*)&w[(size_t)row * CDIM + g8 * 8];
    const float4 v1 = *(const float4*)&w[(size_t)row * CDIM + g8 * 8 + 4];
    uint4 u;
    u.x = packh2(v0.x, v0.y); u.y = packh2(v0.z, v0.w);
    u.z = packh2(v1.x, v1.y); u.w = packh2(v1.z, v1.w);
    *(uint4*)&dst[(size_t)row * C3 + coff + g8 * 8] = u;
}

// ==================== LayerNorm -> single fp16 ====================
__inline__ __device__ float warp_sum(float v) {
    #pragma unroll
    for (int m = 16; m > 0; m >>= 1) v += __shfl_xor_sync(0xffffffffu, v, m);
    return v;
}
__global__ void __launch_bounds__(256) layernorm_h_kernel(
    const float* __restrict__ x, const float* __restrict__ g,
    const float* __restrict__ bt, __half* __restrict__ y)
{
    const int row = blockIdx.x, tid = threadIdx.x;
    const float4 v = ((const float4*)(x + (size_t)row * CDIM))[tid];
    float s  = v.x + v.y + v.z + v.w;
    float ss = v.x*v.x + v.y*v.y + v.z*v.z + v.w*v.w;
    __shared__ float sh1[8], sh2[8];
    s = warp_sum(s); ss = warp_sum(ss);
    const int w = tid >> 5, l = tid & 31;
    if (l == 0) { sh1[w] = s; sh2[w] = ss; }
    __syncthreads();
    if (w == 0) {
        float a = (l < 8) ? sh1[l] : 0.f;
        float b = (l < 8) ? sh2[l] : 0.f;
        a = warp_sum(a); b = warp_sum(b);
        if (l == 0) { sh1[0] = a; sh2[0] = b; }
    }
    __syncthreads();
    const float mean = sh1[0] * (1.0f / CDIM);
    const float var  = sh2[0] * (1.0f / CDIM) - mean * mean;
    const float inv  = rsqrtf(var + 1e-5f);
    const float4 gv = ((const float4*)g)[tid];
    const float4 bv = ((const float4*)bt)[tid];
    uint2 u;
    u.x = packh2((v.x - mean) * inv * gv.x + bv.x,
                 (v.y - mean) * inv * gv.y + bv.y);
    u.y = packh2((v.z - mean) * inv * gv.z + bv.z,
                 (v.w - mean) * inv * gv.w + bv.w);
    *(uint2*)&y[(size_t)row * CDIM + tid * 4] = u;
}

// ==================== tensor-core flash attention (pure fp16) ============
#define FA_QS     18432                 // 128 x 144B
#define FA_KV     9216                  // 64 x 144B
#define FA_STAGE  18432                 // K, V
#define FA_SMEM   (FA_QS + 2 * FA_STAGE)   // 55296

__global__ void __launch_bounds__(256, 2) flash16_kernel(
    const __half* __restrict__ QKV, __half* __restrict__ O)
{
    extern __shared__ char sm[];
    const uint32_t sb = smem_u32(sm);
    const int tid = threadIdx.x, lane = tid & 31, wid = tid >> 5;
    const int qt = gridDim.x - 1 - blockIdx.x;
    const int hh = blockIdx.y, bb = blockIdx.z;
    const int rowbase = bb * TSEQ + qt * 128;
    const int colC = hh * DHEAD;

    auto loadKV = [&](int s, int kt) {
        #pragma unroll
        for (int i = 0; i < 4; i++) {
            const int c = tid + i * 256;
            const int arr = c >> 9;          // 0 K, 1 V
            const int r = (c >> 3) & 63;
            const int seg = c & 7;
            const __half* src = QKV
                + (size_t)(bb * TSEQ + kt * 64 + r) * C3
                + (arr == 0 ? CDIM : 2 * CDIM) + colC + seg * 8;
            cp16(sb + FA_QS + (uint32_t)s * FA_STAGE + arr * FA_KV
                 + r * 144 + seg * 16, src);
        }
    };

    #pragma unroll
    for (int i = 0; i < 2; i++) {
        const int c = tid + i * 256;
        const int r = c >> 2;
        const int seg = c & 3;
        const __half* src = QKV + (size_t)(rowbase + r) * C3 + colC + seg * 16;
        cp16(sb + r * 144 + seg * 32, src);
        cp16(sb + r * 144 + seg * 32 + 16, src + 8);
    }
    cp_commit();
    loadKV(0, 0);
    cp_commit();
    cp_wait<0>();
    __syncthreads();

    uint32_t qh[4][4];
    #pragma unroll
    for (int kf = 0; kf < 4; kf++) {
        const uint32_t qa = sb + (wid * 16 + (lane & 15)) * 144
                               + (kf * 16 + ((lane >> 4) << 3)) * 2;
        ldsm_x4(qh[kf], qa);
    }

    float o[8][4];
    #pragma unroll
    for (int i = 0; i < 8; i++)
        #pragma unroll
        for (int j = 0; j < 4; j++) o[i][j] = 0.f;
    float m0 = -1e30f, m1 = -1e30f, l0 = 0.f, l1 = 0.f;

    const int ktlast = 2 * qt + 1;
    const float SCALE = 0.18033688011112042f;   // 0.125 * log2(e)

    for (int kt = 0; kt <= ktlast; kt++) {
        const int s = kt & 1;
        if (kt < ktlast) { loadKV(s ^ 1, kt + 1); cp_commit(); cp_wait<1>(); }
        else             cp_wait<0>();
        __syncthreads();

        const uint32_t kb = sb + FA_QS + (uint32_t)s * FA_STAGE;
        const uint32_t vb = kb + FA_KV;

        float c[8][4];
        #pragma unroll
        for (int i = 0; i < 8; i++)
            #pragma unroll
            for (int j = 0; j < 4; j++) c[i][j] = 0.f;

        #pragma unroll
        for (int kf = 0; kf < 4; kf++)
            #pragma unroll
            for (int ntp = 0; ntp < 4; ntp++) {
                uint32_t bh[4];
                const uint32_t ka = (ntp * 16 + (lane & 7) + ((lane >> 4) << 3)) * 144
                                  + (kf * 16 + ((lane >> 3) & 1) * 8) * 2;
                ldsm_x4(bh, kb + ka);
                mma_f16(c[2*ntp],   qh[kf], &bh[0]);
                mma_f16(c[2*ntp+1], qh[kf], &bh[2]);
            }

        if (kt >= 2 * qt) {
            const int rg0 = qt * 128 + wid * 16 + (lane >> 2);
            const int cg0 = kt * 64 + (lane & 3) * 2;
            #pragma unroll
            for (int nt = 0; nt < 8; nt++) {
                const int cg = cg0 + nt * 8;
                #pragma unroll
                for (int j = 0; j < 4; j++) {
                    const int r  = rg0 + ((j >> 1) << 3);
                    const int cc = cg + (j & 1);
                    if (cc > r) c[nt][j] = -1e30f;
                }
            }
        }

        float mx0 = -1e30f, mx1 = -1e30f;
        #pragma unroll
        for (int nt = 0; nt < 8; nt++) {
            mx0 = fmaxf(mx0, fmaxf(c[nt][0], c[nt][1]));
            mx1 = fmaxf(mx1, fmaxf(c[nt][2], c[nt][3]));
        }
        mx0 = fmaxf(mx0, __shfl_xor_sync(0xffffffffu, mx0, 1));
        mx0 = fmaxf(mx0, __shfl_xor_sync(0xffffffffu, mx0, 2));
        mx1 = fmaxf(mx1, __shfl_xor_sync(0xffffffffu, mx1, 1));
        mx1 = fmaxf(mx1, __shfl_xor_sync(0xffffffffu, mx1, 2));

        const float nm0 = fmaxf(m0, mx0 * SCALE);
        const float nm1 = fmaxf(m1, mx1 * SCALE);
        const float al0 = fexp2(m0 - nm0);
        const float al1 = fexp2(m1 - nm1);
        m0 = nm0; m1 = nm1;

        float rs0 = 0.f, rs1 = 0.f;
        #pragma unroll
        for (int nt = 0; nt < 8; nt++) {
            float p0 = fexp2(fmaf(c[nt][0], SCALE, -nm0));
            float p1 = fexp2(fmaf(c[nt][1], SCALE, -nm0));
            float p2 = fexp2(fmaf(c[nt][2], SCALE, -nm1));
            float p3 = fexp2(fmaf(c[nt][3], SCALE, -nm1));
            c[nt][0] = p0; c[nt][1] = p1; c[nt][2] = p2; c[nt][3] = p3;
            rs0 += p0 + p1; rs1 += p2 + p3;
        }
        rs0 += __shfl_xor_sync(0xffffffffu, rs0, 1);
        rs0 += __shfl_xor_sync(0xffffffffu, rs0, 2);
        rs1 += __shfl_xor_sync(0xffffffffu, rs1, 1);
        rs1 += __shfl_xor_sync(0xffffffffu, rs1, 2);
        l0 = l0 * al0 + rs0;
        l1 = l1 * al1 + rs1;

        // rescale only when the running max actually moved (al != 1.0 exactly)
        if (__ballot_sync(0xffffffffu, (al0 != 1.0f) || (al1 != 1.0f))) {
            #pragma unroll
            for (int nt = 0; nt < 8; nt++) {
                o[nt][0] *= al0; o[nt][1] *= al0;
                o[nt][2] *= al1; o[nt][3] *= al1;
            }
        }

        #pragma unroll
        for (int kf = 0; kf < 4; kf++) {
            uint32_t ph[4];
            ph[0] = packh2(c[2*kf][0],   c[2*kf][1]);
            ph[1] = packh2(c[2*kf][2],   c[2*kf][3]);
            ph[2] = packh2(c[2*kf+1][0], c[2*kf+1][1]);
            ph[3] = packh2(c[2*kf+1][2], c[2*kf+1][3]);
            #pragma unroll
            for (int ntp = 0; ntp < 4; ntp++) {
                uint32_t vh[4];
                const uint32_t va = (kf * 16 + (lane & 15)) * 144
                                  + (ntp * 16 + ((lane >> 4) << 3)) * 2;
                ldsm_x4t(vh, vb + va);
                mma_f16(o[2*ntp],   ph, &vh[0]);
                mma_f16(o[2*ntp+1], ph, &vh[2]);
            }
        }
        __syncthreads();
    }

    const float il0 = 1.f / l0, il1 = 1.f / l1;
    const int rg = rowbase + wid * 16 + (lane >> 2);
    #pragma unroll
    for (int nt = 0; nt < 8; nt++) {
        const int col = colC + nt * 8 + (lane & 3) * 2;
        *(uint32_t*)&O[(size_t)rg * CDIM + col] =
            packh2(o[nt][0] * il0, o[nt][1] * il0);
        *(uint32_t*)&O[(size_t)(rg + 8) * CDIM + col] =
            packh2(o[nt][2] * il1, o[nt][3] * il1);
    }
}

// ==================== launch ====================
extern "C" void kernel_launch(void* const* d_in, const int* in_sizes, int n_in,
                              void* d_out, int out_size)
{
    (void)in_sizes; (void)n_in; (void)out_size;
    const float* x    = (const float*)d_in[0];
    const float* Wq   = (const float*)d_in[1];
    const float* Wk   = (const float*)d_in[2];
    const float* Wv   = (const float*)d_in[3];
    const float* Wo   = (const float*)d_in[4];
    const float* bo   = (const float*)d_in[5];
    const float* ln1g = (const float*)d_in[6];
    const float* ln1b = (const float*)d_in[7];
    const float* ln2g = (const float*)d_in[8];
    const float* ln2b = (const float*)d_in[9];
    const float* W1   = (const float*)d_in[10];
    const float* b1   = (const float*)d_in[11];
    const float* W2   = (const float*)d_in[12];
    const float* b2   = (const float*)d_in[13];
    float* out = (float*)d_out;

    __half *h, *qkv, *a, *ff;
    float* x1;
    __half *Wqkvh, *Woh, *W1h, *W2h;
    cudaGetSymbolAddress((void**)&h,     g_h);
    cudaGetSymbolAddress((void**)&qkv,   g_qkv);
    cudaGetSymbolAddress((void**)&a,     g_a);
    cudaGetSymbolAddress((void**)&x1,    g_x1);
    cudaGetSymbolAddress((void**)&ff,    g_ff);
    cudaGetSymbolAddress((void**)&Wqkvh, g_Wqkv);
    cudaGetSymbolAddress((void**)&Woh,   g_Wo);
    cudaGetSymbolAddress((void**)&W1h,   g_W1);
    cudaGetSymbolAddress((void**)&W2h,   g_W2);

    static cudaStream_t sside = nullptr;
    static cudaEvent_t evFork = nullptr, evQkvW = nullptr, evWoW = nullptr, evFFNW = nullptr;
    if (!sside) {
        cudaStreamCreateWithFlags(&sside, cudaStreamNonBlocking);
        cudaEventCreateWithFlags(&evFork, cudaEventDisableTiming);
        cudaEventCreateWithFlags(&evQkvW, cudaEventDisableTiming);
        cudaEventCreateWithFlags(&evWoW,  cudaEventDisableTiming);
        cudaEventCreateWithFlags(&evFFNW, cudaEventDisableTiming);
        cudaFuncSetAttribute(gemm16<false, false, false, 2>,
                             cudaFuncAttributeMaxDynamicSharedMemorySize, GEMM_SMEM);
        cudaFuncSetAttribute(gemm16<true, false, true, 0>,
                             cudaFuncAttributeMaxDynamicSharedMemorySize, GEMM_SMEM);
        cudaFuncSetAttribute(gemm16<true, true, false, 2>,
                             cudaFuncAttributeMaxDynamicSharedMemorySize, GEMM_SMEM);
        cudaFuncSetAttribute(flash16_kernel,
                             cudaFuncAttributeMaxDynamicSharedMemorySize, FA_SMEM);
    }

    // ---- fork: weight converts run on the side stream ----
    cudaEventRecord(evFork, 0);
    cudaStreamWaitEvent(sside, evFork, 0);
    wconv_qkv_kernel<<<dim3(512, 1, 3), 256, 0, sside>>>(Wq, Wk, Wv, Wqkvh);
    cudaEventRecord(evQkvW, sside);
    wconv_kernel<<<512, 256, 0, sside>>>(Wo, Woh, CDIM * CDIM / 4);
    cudaEventRecord(evWoW, sside);
    wconv_kernel<<<1024, 256, 0, sside>>>(W1, W1h, CDIM * FDIM / 4);
    wconv_kernel<<<1024, 256, 0, sside>>>(W2, W2h, FDIM * CDIM / 4);
    cudaEventRecord(evFFNW, sside);

    // ---- main stream ----
    layernorm_h_kernel<<<MTOT, 256>>>(x, ln1g, ln1b, h);

    cudaStreamWaitEvent(0, evQkvW, 0);
    gemm16<false, false, false, 2><<<dim3(C3 / 128, MTOT / 128), GT, GEMM_SMEM>>>(
        h, Wqkvh, nullptr, nullptr, nullptr, qkv, C3, CDIM);
    flash16_kernel<<<dim3(TSEQ / 128, HEADS, BB), 256, FA_SMEM>>>(qkv, a);

    cudaStreamWaitEvent(0, evWoW, 0);
    gemm16<true, false, true, 0><<<dim3(CDIM / 128, MTOT / 128), GT, GEMM_SMEM>>>(
        a, Woh, bo, x, x1, nullptr, CDIM, CDIM);
    layernorm_h_kernel<<<MTOT, 256>>>(x1, ln2g, ln2b, h);

    cudaStreamWaitEvent(0, evFFNW, 0);
    gemm16<true, true, false, 2><<<dim3(FDIM / 128, MTOT / 128), GT, GEMM_SMEM>>>(
        h, W1h, b1, nullptr, nullptr, ff, FDIM, CDIM);
    gemm16<true, false, true, 0><<<dim3(CDIM / 128, MTOT / 128), GT, GEMM_SMEM>>>(
        ff, W2h, b2, x1, out, nullptr, CDIM, FDIM);
}

// round 14
// speedup vs baseline: 1.0280x; 1.0280x over previous
#include <cuda_runtime.h>
#include <cuda_fp16.h>
#include <cstdint>
#include <math.h>

#define BB    4
#define TSEQ  2048
#define CDIM  1024
#define HEADS 16
#define DHEAD 64
#define MTOT  (BB * TSEQ)
#define FDIM  (4 * CDIM)
#define C3    (3 * CDIM)

// -------- scratch (device globals) --------
__device__ __half g_h   [MTOT * CDIM];
__device__ __half g_qkv [MTOT * C3];
__device__ __half g_a   [MTOT * CDIM];
__device__ float  g_x1  [MTOT * CDIM];
__device__ __half g_ff  [MTOT * FDIM];
__device__ __half g_Wqkv[CDIM * C3];
__device__ __half g_Wo[CDIM * CDIM];
__device__ __half g_W1[CDIM * FDIM], g_W2[FDIM * CDIM];

// -------- PTX helpers (plain sm_80+ only) --------
__device__ __forceinline__ uint32_t smem_u32(const void* p) {
    uint32_t a;
    asm("{ .reg .u64 t; cvta.to.shared.u64 t, %1; cvt.u32.u64 %0, t; }" : "=r"(a) : "l"(p));
    return a;
}
__device__ __forceinline__ void cp16(uint32_t dst, const void* src) {
    asm volatile("cp.async.cg.shared.global [%0], [%1], 16;" :: "r"(dst), "l"(src));
}
__device__ __forceinline__ void cp_commit() { asm volatile("cp.async.commit_group;"); }
template<int N> __device__ __forceinline__ void cp_wait() {
    asm volatile("cp.async.wait_group %0;" :: "n"(N));
}
__device__ __forceinline__ void ldsm_x4(uint32_t* r, uint32_t a) {
    asm volatile("ldmatrix.sync.aligned.m8n8.x4.shared.b16 {%0,%1,%2,%3}, [%4];"
                 : "=r"(r[0]), "=r"(r[1]), "=r"(r[2]), "=r"(r[3]) : "r"(a));
}
__device__ __forceinline__ void ldsm_x4t(uint32_t* r, uint32_t a) {
    asm volatile("ldmatrix.sync.aligned.m8n8.x4.trans.shared.b16 {%0,%1,%2,%3}, [%4];"
                 : "=r"(r[0]), "=r"(r[1]), "=r"(r[2]), "=r"(r[3]) : "r"(a));
}
__device__ __forceinline__ void mma_f16(float* c, const uint32_t* a, const uint32_t* b) {
    asm volatile(
        "mma.sync.aligned.m16n8k16.row.col.f32.f16.f16.f32 "
        "{%0,%1,%2,%3}, {%4,%5,%6,%7}, {%8,%9}, {%0,%1,%2,%3};"
        : "+f"(c[0]), "+f"(c[1]), "+f"(c[2]), "+f"(c[3])
        : "r"(a[0]), "r"(a[1]), "r"(a[2]), "r"(a[3]), "r"(b[0]), "r"(b[1]));
}
__device__ __forceinline__ uint32_t packh2(float a, float b) {
    __half2 h = __floats2half2_rn(a, b);
    return *(uint32_t*)&h;
}
__device__ __forceinline__ float fexp2(float t) {   // fast 2^t, t<=0
    t = fmaxf(t, -126.0f);
    const float mag = 12582912.0f;
    float r = t + mag;
    uint32_t ui = __float_as_uint(r);
    float f = t - (r - mag);
    float p = 1.3333558146e-3f;
    p = fmaf(p, f, 9.6181291076e-3f);
    p = fmaf(p, f, 5.5504108664e-2f);
    p = fmaf(p, f, 2.4022650696e-1f);
    p = fmaf(p, f, 6.9314718056e-1f);
    p = fmaf(p, f, 1.0f);
    return __uint_as_float(__float_as_uint(p) + (ui << 23));
}

// ==================== fp16 GEMM: 128x128 CTA, 64x32 warp tile =============
// 8 warps (2x4), BK=32, 4-stage cp.async, 2 CTAs/SM, ONE barrier per chunk.
// OUT: 0 = fp32 (+res), 2 = single fp16.
#define GT       256
#define GA3      10240               // 128 x 80B
#define GB3      8704                // 32 x 272B
#define GSTG     (GA3 + GB3)         // 18944
#define GEMM_SMEM (4 * GSTG)         // 75776

template<bool BIAS, bool RELU, bool RES, int OUT>
__global__ void __launch_bounds__(GT, 2) gemm16(
    const __half* __restrict__ A, const __half* __restrict__ B,
    const float* __restrict__ bias, const float* __restrict__ res,
    float* __restrict__ Cf, __half* __restrict__ Ch,
    int N, int K)
{
    extern __shared__ char sm[];
    const uint32_t sb = smem_u32(sm);
    const int tid = threadIdx.x, lane = tid & 31, wid = tid >> 5;
    const int wm = (wid >> 2) * 64, wn = (wid & 3) * 32;
    const int m0 = blockIdx.y * 128, n0 = blockIdx.x * 128;

    auto load_stage = [&](int s, int c) {
        const int kc = c << 5;
        const uint32_t st = sb + (uint32_t)s * GSTG;
        const int row = tid >> 1, sg0 = (tid & 1) << 1;
        const size_t g = (size_t)(m0 + row) * K + kc + sg0 * 8;
        const uint32_t so = st + row * 80 + sg0 * 16;
        cp16(so,      A + g);
        cp16(so + 16, A + g + 8);
        const int br = tid >> 4, seg = tid & 15;
        const size_t gb = (size_t)(kc + br) * N + n0 + seg * 8;
        const uint32_t sob = st + GA3 + br * 272 + seg * 16;
        cp16(sob, B + gb);
        cp16(sob + 16 * 272, B + gb + (size_t)16 * N);
    };

    float acc[4][4][4];
    #pragma unroll
    for (int a = 0; a < 4; a++)
        #pragma unroll
        for (int b = 0; b < 4; b++)
            #pragma unroll
            for (int d = 0; d < 4; d++) acc[a][b][d] = 0.f;

    const int NC = K >> 5;
    load_stage(0, 0); cp_commit();
    load_stage(1, 1); cp_commit();
    load_stage(2, 2); cp_commit();

    for (int c = 0; c < NC; c++) {
        const int s = c & 3;
        if (c + 2 < NC)      cp_wait<2>();
        else if (c + 1 < NC) cp_wait<1>();
        else                 cp_wait<0>();
        __syncthreads();
        // prefetch into (c+3)&3 — that stage's compute ended at c-1, protected
        // by the barrier above (all warps have passed compute c-1).
        if (c + 3 < NC) { load_stage((c + 3) & 3, c + 3); cp_commit(); }

        const uint32_t aoff = sb + (uint32_t)s * GSTG;
        const uint32_t boff = aoff + GA3;
        #pragma unroll
        for (int ks = 0; ks < 2; ks++) {
            uint32_t bfr[4][2];
            #pragma unroll
            for (int ntp = 0; ntp < 2; ntp++) {
                uint32_t r[4];
                ldsm_x4t(r, boff + (ks * 16 + (lane & 15)) * 272
                              + (wn + ntp * 16 + ((lane >> 4) << 3)) * 2);
                bfr[2*ntp][0] = r[0]; bfr[2*ntp][1] = r[1];
                bfr[2*ntp+1][0] = r[2]; bfr[2*ntp+1][1] = r[3];
            }
            #pragma unroll
            for (int mt = 0; mt < 4; mt++) {
                uint32_t ah[4];
                ldsm_x4(ah, aoff + (wm + mt * 16 + (lane & 15)) * 80
                              + ks * 32 + ((lane >> 4) << 4));
                #pragma unroll
                for (int nt = 0; nt < 4; nt++)
                    mma_f16(acc[mt][nt], ah, bfr[nt]);
            }
        }
    }

    // epilogue reads only registers; no barrier needed
    #pragma unroll
    for (int mt = 0; mt < 4; mt++)
        #pragma unroll
        for (int nt = 0; nt < 4; nt++)
            #pragma unroll
            for (int hf = 0; hf < 2; hf++) {
                const int row = m0 + wm + mt * 16 + (lane >> 2) + hf * 8;
                const int col = n0 + wn + nt * 8 + (lane & 3) * 2;
                float v0 = acc[mt][nt][hf * 2 + 0];
                float v1 = acc[mt][nt][hf * 2 + 1];
                if (BIAS) { v0 += bias[col]; v1 += bias[col + 1]; }
                if (RELU) { v0 = fmaxf(v0, 0.f); v1 = fmaxf(v1, 0.f); }
                if (RES) {
                    const float2 rr = *(const float2*)&res[(size_t)row * N + col];
                    v0 += rr.x; v1 += rr.y;
                }
                if (OUT == 2) {
                    *(uint32_t*)&Ch[(size_t)row * N + col] = packh2(v0, v1);
                } else {
                    float2 o; o.x = v0; o.y = v1;
                    *(float2*)&Cf[(size_t)row * N + col] = o;
                }
            }
}

// ==================== weight converts ====================
__global__ void __launch_bounds__(256) wconv_kernel(
    const float* __restrict__ w, __half* __restrict__ o, int n4)
{
    for (int i = blockIdx.x * blockDim.x + threadIdx.x; i < n4;
         i += gridDim.x * blockDim.x) {
        const float4 v = ((const float4*)w)[i];
        const __half2 a = __floats2half2_rn(v.x, v.y);
        const __half2 b = __floats2half2_rn(v.z, v.w);
        uint2 u; u.x = *(const uint32_t*)&a; u.y = *(const uint32_t*)&b;
        *(uint2*)&o[(size_t)i * 4] = u;
    }
}
__global__ void __launch_bounds__(256) wconv_qkv_kernel(
    const float* __restrict__ Wq, const float* __restrict__ Wk,
    const float* __restrict__ Wv, __half* __restrict__ dst)
{
    const int z = blockIdx.z;
    const float* w = (z == 0) ? Wq : (z == 1) ? Wk : Wv;
    const int coff = z * CDIM;
    const int idx = blockIdx.x * blockDim.x + threadIdx.x;
    const int row = idx >> 7;
    const int g8  = idx & 127;
    const float4 v0 = *(const float4*)&w[(size_t)row * CDIM + g8 * 8];
    const float4 v1 = *(const float4*)&w[(size_t)row * CDIM + g8 * 8 + 4];
    uint4 u;
    u.x = packh2(v0.x, v0.y); u.y = packh2(v0.z, v0.w);
    u.z = packh2(v1.x, v1.y); u.w = packh2(v1.z, v1.w);
    *(uint4*)&dst[(size_t)row * C3 + coff + g8 * 8] = u;
}

// ==================== LayerNorm -> single fp16 ====================
__inline__ __device__ float warp_sum(float v) {
    #pragma unroll
    for (int m = 16; m > 0; m >>= 1) v += __shfl_xor_sync(0xffffffffu, v, m);
    return v;
}
__global__ void __launch_bounds__(256) layernorm_h_kernel(
    const float* __restrict__ x, const float* __restrict__ g,
    const float* __restrict__ bt, __half* __restrict__ y)
{
    const int row = blockIdx.x, tid = threadIdx.x;
    const float4 v = ((const float4*)(x + (size_t)row * CDIM))[tid];
    float s  = v.x + v.y + v.z + v.w;
    float ss = v.x*v.x + v.y*v.y + v.z*v.z + v.w*v.w;
    __shared__ float sh1[8], sh2[8];
    s = warp_sum(s); ss = warp_sum(ss);
    const int w = tid >> 5, l = tid & 31;
    if (l == 0) { sh1[w] = s; sh2[w] = ss; }
    __syncthreads();
    if (w == 0) {
        float a = (l < 8) ? sh1[l] : 0.f;
        float b = (l < 8) ? sh2[l] : 0.f;
        a = warp_sum(a); b = warp_sum(b);
        if (l == 0) { sh1[0] = a; sh2[0] = b; }
    }
    __syncthreads();
    const float mean = sh1[0] * (1.0f / CDIM);
    const float var  = sh2[0] * (1.0f / CDIM) - mean * mean;
    const float inv  = rsqrtf(var + 1e-5f);
    const float4 gv = ((const float4*)g)[tid];
    const float4 bv = ((const float4*)bt)[tid];
    uint2 u;
    u.x = packh2((v.x - mean) * inv * gv.x + bv.x,
                 (v.y - mean) * inv * gv.y + bv.y);
    u.y = packh2((v.z - mean) * inv * gv.z + bv.z,
                 (v.w - mean) * inv * gv.w + bv.w);
    *(uint2*)&y[(size_t)row * CDIM + tid * 4] = u;
}

// ==================== tensor-core flash attention (pure fp16) ============
#define FA_QS     18432                 // 128 x 144B
#define FA_KV     9216                  // 64 x 144B
#define FA_STAGE  18432                 // K, V
#define FA_SMEM   (FA_QS + 2 * FA_STAGE)   // 55296

__global__ void __launch_bounds__(256, 2) flash16_kernel(
    const __half* __restrict__ QKV, __half* __restrict__ O)
{
    extern __shared__ char sm[];
    const uint32_t sb = smem_u32(sm);
    const int tid = threadIdx.x, lane = tid & 31, wid = tid >> 5;
    const int qt = gridDim.x - 1 - blockIdx.x;
    const int hh = blockIdx.y, bb = blockIdx.z;
    const int rowbase = bb * TSEQ + qt * 128;
    const int colC = hh * DHEAD;

    auto loadKV = [&](int s, int kt) {
        #pragma unroll
        for (int i = 0; i < 4; i++) {
            const int c = tid + i * 256;
            const int arr = c >> 9;          // 0 K, 1 V
            const int r = (c >> 3) & 63;
            const int seg = c & 7;
            const __half* src = QKV
                + (size_t)(bb * TSEQ + kt * 64 + r) * C3
                + (arr == 0 ? CDIM : 2 * CDIM) + colC + seg * 8;
            cp16(sb + FA_QS + (uint32_t)s * FA_STAGE + arr * FA_KV
                 + r * 144 + seg * 16, src);
        }
    };

    #pragma unroll
    for (int i = 0; i < 2; i++) {
        const int c = tid + i * 256;
        const int r = c >> 2;
        const int seg = c & 3;
        const __half* src = QKV + (size_t)(rowbase + r) * C3 + colC + seg * 16;
        cp16(sb + r * 144 + seg * 32, src);
        cp16(sb + r * 144 + seg * 32 + 16, src + 8);
    }
    cp_commit();
    loadKV(0, 0);
    cp_commit();
    cp_wait<0>();
    __syncthreads();

    uint32_t qh[4][4];
    #pragma unroll
    for (int kf = 0; kf < 4; kf++) {
        const uint32_t qa = sb + (wid * 16 + (lane & 15)) * 144
                               + (kf * 16 + ((lane >> 4) << 3)) * 2;
        ldsm_x4(qh[kf], qa);
    }

    float o[8][4];
    #pragma unroll
    for (int i = 0; i < 8; i++)
        #pragma unroll
        for (int j = 0; j < 4; j++) o[i][j] = 0.f;
    float m0 = -1e30f, m1 = -1e30f, l0 = 0.f, l1 = 0.f;

    const int ktlast = 2 * qt + 1;
    const float SCALE = 0.18033688011112042f;   // 0.125 * log2(e)

    for (int kt = 0; kt <= ktlast; kt++) {
        const int s = kt & 1;
        if (kt < ktlast) { loadKV(s ^ 1, kt + 1); cp_commit(); cp_wait<1>(); }
        else             cp_wait<0>();
        __syncthreads();

        const uint32_t kb = sb + FA_QS + (uint32_t)s * FA_STAGE;
        const uint32_t vb = kb + FA_KV;

        float c[8][4];
        #pragma unroll
        for (int i = 0; i < 8; i++)
            #pragma unroll
            for (int j = 0; j < 4; j++) c[i][j] = 0.f;

        #pragma unroll
        for (int kf = 0; kf < 4; kf++)
            #pragma unroll
            for (int ntp = 0; ntp < 4; ntp++) {
                uint32_t bh[4];
                const uint32_t ka = (ntp * 16 + (lane & 7) + ((lane >> 4) << 3)) * 144
                                  + (kf * 16 + ((lane >> 3) & 1) * 8) * 2;
                ldsm_x4(bh, kb + ka);
                mma_f16(c[2*ntp],   qh[kf], &bh[0]);
                mma_f16(c[2*ntp+1], qh[kf], &bh[2]);
            }

        if (kt >= 2 * qt) {
            const int rg0 = qt * 128 + wid * 16 + (lane >> 2);
            const int cg0 = kt * 64 + (lane & 3) * 2;
            #pragma unroll
            for (int nt = 0; nt < 8; nt++) {
                const int cg = cg0 + nt * 8;
                #pragma unroll
                for (int j = 0; j < 4; j++) {
                    const int r  = rg0 + ((j >> 1) << 3);
                    const int cc = cg + (j & 1);
                    if (cc > r) c[nt][j] = -1e30f;
                }
            }
        }

        float mx0 = -1e30f, mx1 = -1e30f;
        #pragma unroll
        for (int nt = 0; nt < 8; nt++) {
            mx0 = fmaxf(mx0, fmaxf(c[nt][0], c[nt][1]));
            mx1 = fmaxf(mx1, fmaxf(c[nt][2], c[nt][3]));
        }
        mx0 = fmaxf(mx0, __shfl_xor_sync(0xffffffffu, mx0, 1));
        mx0 = fmaxf(mx0, __shfl_xor_sync(0xffffffffu, mx0, 2));
        mx1 = fmaxf(mx1, __shfl_xor_sync(0xffffffffu, mx1, 1));
        mx1 = fmaxf(mx1, __shfl_xor_sync(0xffffffffu, mx1, 2));

        const float nm0 = fmaxf(m0, mx0 * SCALE);
        const float nm1 = fmaxf(m1, mx1 * SCALE);
        const float al0 = fexp2(m0 - nm0);
        const float al1 = fexp2(m1 - nm1);
        m0 = nm0; m1 = nm1;

        float rs0 = 0.f, rs1 = 0.f;
        #pragma unroll
        for (int nt = 0; nt < 8; nt++) {
            float p0 = fexp2(fmaf(c[nt][0], SCALE, -nm0));
            float p1 = fexp2(fmaf(c[nt][1], SCALE, -nm0));
            float p2 = fexp2(fmaf(c[nt][2], SCALE, -nm1));
            float p3 = fexp2(fmaf(c[nt][3], SCALE, -nm1));
            c[nt][0] = p0; c[nt][1] = p1; c[nt][2] = p2; c[nt][3] = p3;
            rs0 += p0 + p1; rs1 += p2 + p3;
        }
        rs0 += __shfl_xor_sync(0xffffffffu, rs0, 1);
        rs0 += __shfl_xor_sync(0xffffffffu, rs0, 2);
        rs1 += __shfl_xor_sync(0xffffffffu, rs1, 1);
        rs1 += __shfl_xor_sync(0xffffffffu, rs1, 2);
        l0 = l0 * al0 + rs0;
        l1 = l1 * al1 + rs1;

        // rescale only when the running max actually moved (al != 1.0 exactly)
        if (__ballot_sync(0xffffffffu, (al0 != 1.0f) || (al1 != 1.0f))) {
            #pragma unroll
            for (int nt = 0; nt < 8; nt++) {
                o[nt][0] *= al0; o[nt][1] *= al0;
                o[nt][2] *= al1; o[nt][3] *= al1;
            }
        }

        #pragma unroll
        for (int kf = 0; kf < 4; kf++) {
            uint32_t ph[4];
            ph[0] = packh2(c[2*kf][0],   c[2*kf][1]);
            ph[1] = packh2(c[2*kf][2],   c[2*kf][3]);
            ph[2] = packh2(c[2*kf+1][0], c[2*kf+1][1]);
            ph[3] = packh2(c[2*kf+1][2], c[2*kf+1][3]);
            #pragma unroll
            for (int ntp = 0; ntp < 4; ntp++) {
                uint32_t vh[4];
                const uint32_t va = (kf * 16 + (lane & 15)) * 144
                                  + (ntp * 16 + ((lane >> 4) << 3)) * 2;
                ldsm_x4t(vh, vb + va);
                mma_f16(o[2*ntp],   ph, &vh[0]);
                mma_f16(o[2*ntp+1], ph, &vh[2]);
            }
        }
        __syncthreads();
    }

    const float il0 = 1.f / l0, il1 = 1.f / l1;
    const int rg = rowbase + wid * 16 + (lane >> 2);
    #pragma unroll
    for (int nt = 0; nt < 8; nt++) {
        const int col = colC + nt * 8 + (lane & 3) * 2;
        *(uint32_t*)&O[(size_t)rg * CDIM + col] =
            packh2(o[nt][0] * il0, o[nt][1] * il0);
        *(uint32_t*)&O[(size_t)(rg + 8) * CDIM + col] =
            packh2(o[nt][2] * il1, o[nt][3] * il1);
    }
}

// ==================== launch ====================
extern "C" void kernel_launch(void* const* d_in, const int* in_sizes, int n_in,
                              void* d_out, int out_size)
{
    (void)in_sizes; (void)n_in; (void)out_size;
    const float* x    = (const float*)d_in[0];
    const float* Wq   = (const float*)d_in[1];
    const float* Wk   = (const float*)d_in[2];
    const float* Wv   = (const float*)d_in[3];
    const float* Wo   = (const float*)d_in[4];
    const float* bo   = (const float*)d_in[5];
    const float* ln1g = (const float*)d_in[6];
    const float* ln1b = (const float*)d_in[7];
    const float* ln2g = (const float*)d_in[8];
    const float* ln2b = (const float*)d_in[9];
    const float* W1   = (const float*)d_in[10];
    const float* b1   = (const float*)d_in[11];
    const float* W2   = (const float*)d_in[12];
    const float* b2   = (const float*)d_in[13];
    float* out = (float*)d_out;

    __half *h, *qkv, *a, *ff;
    float* x1;
    __half *Wqkvh, *Woh, *W1h, *W2h;
    cudaGetSymbolAddress((void**)&h,     g_h);
    cudaGetSymbolAddress((void**)&qkv,   g_qkv);
    cudaGetSymbolAddress((void**)&a,     g_a);
    cudaGetSymbolAddress((void**)&x1,    g_x1);
    cudaGetSymbolAddress((void**)&ff,    g_ff);
    cudaGetSymbolAddress((void**)&Wqkvh, g_Wqkv);
    cudaGetSymbolAddress((void**)&Woh,   g_Wo);
    cudaGetSymbolAddress((void**)&W1h,   g_W1);
    cudaGetSymbolAddress((void**)&W2h,   g_W2);

    static cudaStream_t sside = nullptr;
    static cudaEvent_t evFork = nullptr, evQkvW = nullptr, evWoW = nullptr, evFFNW = nullptr;
    if (!sside) {
        cudaStreamCreateWithFlags(&sside, cudaStreamNonBlocking);
        cudaEventCreateWithFlags(&evFork, cudaEventDisableTiming);
        cudaEventCreateWithFlags(&evQkvW, cudaEventDisableTiming);
        cudaEventCreateWithFlags(&evWoW,  cudaEventDisableTiming);
        cudaEventCreateWithFlags(&evFFNW, cudaEventDisableTiming);
        cudaFuncSetAttribute(gemm16<false, false, false, 2>,
                             cudaFuncAttributeMaxDynamicSharedMemorySize, GEMM_SMEM);
        cudaFuncSetAttribute(gemm16<true, false, true, 0>,
                             cudaFuncAttributeMaxDynamicSharedMemorySize, GEMM_SMEM);
        cudaFuncSetAttribute(gemm16<true, true, false, 2>,
                             cudaFuncAttributeMaxDynamicSharedMemorySize, GEMM_SMEM);
        cudaFuncSetAttribute(flash16_kernel,
                             cudaFuncAttributeMaxDynamicSharedMemorySize, FA_SMEM);
    }

    // ---- fork: weight converts run on the side stream ----
    cudaEventRecord(evFork, 0);
    cudaStreamWaitEvent(sside, evFork, 0);
    wconv_qkv_kernel<<<dim3(512, 1, 3), 256, 0, sside>>>(Wq, Wk, Wv, Wqkvh);
    cudaEventRecord(evQkvW, sside);
    wconv_kernel<<<512, 256, 0, sside>>>(Wo, Woh, CDIM * CDIM / 4);
    cudaEventRecord(evWoW, sside);
    wconv_kernel<<<1024, 256, 0, sside>>>(W1, W1h, CDIM * FDIM / 4);
    wconv_kernel<<<1024, 256, 0, sside>>>(W2, W2h, FDIM * CDIM / 4);
    cudaEventRecord(evFFNW, sside);

    // ---- main stream ----
    layernorm_h_kernel<<<MTOT, 256>>>(x, ln1g, ln1b, h);

    cudaStreamWaitEvent(0, evQkvW, 0);
    gemm16<false, false, false, 2><<<dim3(C3 / 128, MTOT / 128), GT, GEMM_SMEM>>>(
        h, Wqkvh, nullptr, nullptr, nullptr, qkv, C3, CDIM);
    flash16_kernel<<<dim3(TSEQ / 128, HEADS, BB), 256, FA_SMEM>>>(qkv, a);

    cudaStreamWaitEvent(0, evWoW, 0);
    gemm16<true, false, true, 0><<<dim3(CDIM / 128, MTOT / 128), GT, GEMM_SMEM>>>(
        a, Woh, bo, x, x1, nullptr, CDIM, CDIM);
    layernorm_h_kernel<<<MTOT, 256>>>(x1, ln2g, ln2b, h);

    cudaStreamWaitEvent(0, evFFNW, 0);
    gemm16<true, true, false, 2><<<dim3(FDIM / 128, MTOT / 128), GT, GEMM_SMEM>>>(
        h, W1h, b1, nullptr, nullptr, ff, FDIM, CDIM);
    gemm16<true, false, true, 0><<<dim3(CDIM / 128, MTOT / 128), GT, GEMM_SMEM>>>(
        ff, W2h, b2, x1, out, nullptr, CDIM, FDIM);
}